// round 7
// baseline (speedup 1.0000x reference)
#include <cuda_runtime.h>
#include <math.h>
#include <stdint.h>

static constexpr int BB   = 64;
static constexpr int LL   = 128;
static constexpr int EMBD = 300;
static constexpr int HH   = 256;
static constexpr int NE   = 34;
static constexpr int NA   = 36;

// ---------------- scratch ----------------
__device__ float g_xT  [300 * 8192];              // [e][m=t*64+b]
__device__ float g_WT  [2 * 300 * 1024];          // [dir][k][row]
__device__ float g_xg  [LL * 2 * 4 * HH * BB];    // [t][dir][g][u][b]
__device__ float g_hsT [LL * 2 * HH * BB];        // [t][dir][u][b]
__device__ float g_evbase[LL * BB * NE];          // [t*64+b][34]
__device__ float g_base36[LL * BB * NA];          // [pos*64+b][36]
__device__ float g_thadd [LL * BB * NA];          // [t*64+b][36]
__device__ float g_Wcat [112 * 512];
__device__ float g_WeGT [33 * 34];
__device__ float g_WaGT [35 * 36];
__device__ unsigned char g_emask[BB * LL];
__device__ unsigned int g_barQ[8];                // [dir][quarter]

// ---------------- f32x2 helpers ----------------
__device__ __forceinline__ uint64_t pk2(float x, float y) {
    uint64_t r; asm("mov.b64 %0,{%1,%2};" : "=l"(r) : "f"(x), "f"(y)); return r;
}
__device__ __forceinline__ uint64_t ffma2(uint64_t a, uint64_t b, uint64_t c) {
    uint64_t d; asm("fma.rn.f32x2 %0,%1,%2,%3;" : "=l"(d) : "l"(a), "l"(b), "l"(c)); return d;
}
__device__ __forceinline__ uint64_t addx2(uint64_t a, uint64_t b) {
    uint64_t d; asm("add.rn.f32x2 %0,%1,%2;" : "=l"(d) : "l"(a), "l"(b)); return d;
}
__device__ __forceinline__ float2 up2(uint64_t v) {
    float2 r; asm("mov.b64 {%0,%1},%2;" : "=f"(r.x), "=f"(r.y) : "l"(v)); return r;
}

// ---------------- kernel 1: embedding gather (transposed out) ----------------
__global__ void k_gather(const int* __restrict__ ids, const float* __restrict__ emb) {
    int t = blockIdx.x;
    int tid = threadIdx.x;
    int b = tid >> 2, q = tid & 3;
    int id = ids[b * LL + t];
    const float4* src = (const float4*)(emb + (size_t)id * EMBD);
#pragma unroll
    for (int j = 0; j < 19; j++) {
        int e4 = q + j * 4;
        if (e4 < 75) {
            float4 v = src[e4];
            int e = e4 * 4;
            size_t base = (size_t)e * 8192 + t * 64 + b;
            g_xT[base]          = v.x;
            g_xT[base + 8192]   = v.y;
            g_xT[base + 16384]  = v.z;
            g_xT[base + 24576]  = v.w;
        }
    }
}

// ---------------- kernel 1b: transpose W_ih (both dirs) ----------------
__global__ void k_transW(const float* __restrict__ Wf, const float* __restrict__ Wb) {
    __shared__ float ts[32][33];
    const float* W = blockIdx.z ? Wb : Wf;
    float* out = g_WT + (size_t)blockIdx.z * 300 * 1024;
    int n0 = blockIdx.x * 32, k0 = blockIdx.y * 32;
    int tx = threadIdx.x, ty = threadIdx.y;
#pragma unroll
    for (int r = 0; r < 4; r++) {
        int row = ty + r * 8;
        int k = k0 + tx;
        if (k < 300) ts[row][tx] = W[(size_t)(n0 + row) * 300 + k];
    }
    __syncthreads();
#pragma unroll
    for (int r = 0; r < 4; r++) {
        int row = ty + r * 8;
        int k = k0 + row;
        if (k < 300) out[(size_t)k * 1024 + n0 + tx] = ts[tx][row];
    }
}

// ---------------- kernel 2: pack decode weights + reset counters ----------------
__global__ void k_prep(const float* __restrict__ We, const float* __restrict__ Wa) {
    if (blockIdx.x == 0 && threadIdx.x < 8) g_barQ[threadIdx.x] = 0u;
    int tid = blockIdx.x * blockDim.x + threadIdx.x;
    int stride = gridDim.x * blockDim.x;
    for (int i = tid; i < 112 * 512; i += stride) {
        int n = i >> 9, k = i & 511;
        float v = 0.f;
        if (n < 34)       v = We[n * 545 + k];
        else if (n < 70)  v = Wa[(n - 34) * 1059 + k];
        else if (n < 106) v = Wa[(n - 70) * 1059 + 512 + k];
        g_Wcat[i] = v;
    }
    for (int i = tid; i < 33 * 34; i += stride) {
        int j = i / 34, e = i % 34;
        g_WeGT[i] = We[e * 545 + 512 + j];
    }
    for (int i = tid; i < 35 * 36; i += stride) {
        int j = i / 36, e = i % 36;
        g_WaGT[i] = Wa[e * 1059 + 1024 + j];
    }
}

// ---------------- kernel 3: input GEMM, 128x128 tiles, dup'd W in smem ----------------
__global__ void __launch_bounds__(256, 2)
k_gemm1(const float* __restrict__ bf, const float* __restrict__ bbv) {
    __shared__ uint64_t Wsd[30 * 128];   // dup'd W: 30 KB
    __shared__ float    Xs[30 * 128];    // 15 KB
    int nb = blockIdx.x;
    int mb = blockIdx.y;
    int dir = nb >> 3;
    int j0 = (nb & 7) * 128;
    int m0 = mb * 128;
    const float* WT = g_WT + (size_t)dir * 300 * 1024;
    const float* bias = dir ? bbv : bf;
    int tid = threadIdx.x;
    int tw = tid & 15, tx = tid >> 4;
    uint64_t acc[8][4];
#pragma unroll
    for (int i = 0; i < 8; i++)
#pragma unroll
        for (int j = 0; j < 4; j++) acc[i][j] = 0ull;

    for (int kt = 0; kt < 10; kt++) {
        int k0 = kt * 30;
#pragma unroll
        for (int i = 0; i < 15; i++) {
            int idx = i * 256 + tid;
            int kk = idx >> 7, mm = idx & 127;
            Xs[idx] = g_xT[(size_t)(k0 + kk) * 8192 + m0 + mm];
            float wv = WT[(size_t)(k0 + kk) * 1024 + j0 + mm];
            Wsd[idx] = pk2(wv, wv);
        }
        __syncthreads();
#pragma unroll 5
        for (int kk = 0; kk < 30; kk++) {
            ulonglong2 w01 = *(const ulonglong2*)&Wsd[kk * 128 + tw * 8];
            ulonglong2 w23 = *(const ulonglong2*)&Wsd[kk * 128 + tw * 8 + 2];
            ulonglong2 w45 = *(const ulonglong2*)&Wsd[kk * 128 + tw * 8 + 4];
            ulonglong2 w67 = *(const ulonglong2*)&Wsd[kk * 128 + tw * 8 + 6];
            ulonglong2 x01 = *(const ulonglong2*)&Xs[kk * 128 + tx * 8];
            ulonglong2 x23 = *(const ulonglong2*)&Xs[kk * 128 + tx * 8 + 4];
            acc[0][0] = ffma2(w01.x, x01.x, acc[0][0]); acc[0][1] = ffma2(w01.x, x01.y, acc[0][1]);
            acc[0][2] = ffma2(w01.x, x23.x, acc[0][2]); acc[0][3] = ffma2(w01.x, x23.y, acc[0][3]);
            acc[1][0] = ffma2(w01.y, x01.x, acc[1][0]); acc[1][1] = ffma2(w01.y, x01.y, acc[1][1]);
            acc[1][2] = ffma2(w01.y, x23.x, acc[1][2]); acc[1][3] = ffma2(w01.y, x23.y, acc[1][3]);
            acc[2][0] = ffma2(w23.x, x01.x, acc[2][0]); acc[2][1] = ffma2(w23.x, x01.y, acc[2][1]);
            acc[2][2] = ffma2(w23.x, x23.x, acc[2][2]); acc[2][3] = ffma2(w23.x, x23.y, acc[2][3]);
            acc[3][0] = ffma2(w23.y, x01.x, acc[3][0]); acc[3][1] = ffma2(w23.y, x01.y, acc[3][1]);
            acc[3][2] = ffma2(w23.y, x23.x, acc[3][2]); acc[3][3] = ffma2(w23.y, x23.y, acc[3][3]);
            acc[4][0] = ffma2(w45.x, x01.x, acc[4][0]); acc[4][1] = ffma2(w45.x, x01.y, acc[4][1]);
            acc[4][2] = ffma2(w45.x, x23.x, acc[4][2]); acc[4][3] = ffma2(w45.x, x23.y, acc[4][3]);
            acc[5][0] = ffma2(w45.y, x01.x, acc[5][0]); acc[5][1] = ffma2(w45.y, x01.y, acc[5][1]);
            acc[5][2] = ffma2(w45.y, x23.x, acc[5][2]); acc[5][3] = ffma2(w45.y, x23.y, acc[5][3]);
            acc[6][0] = ffma2(w67.x, x01.x, acc[6][0]); acc[6][1] = ffma2(w67.x, x01.y, acc[6][1]);
            acc[6][2] = ffma2(w67.x, x23.x, acc[6][2]); acc[6][3] = ffma2(w67.x, x23.y, acc[6][3]);
            acc[7][0] = ffma2(w67.y, x01.x, acc[7][0]); acc[7][1] = ffma2(w67.y, x01.y, acc[7][1]);
            acc[7][2] = ffma2(w67.y, x23.x, acc[7][2]); acc[7][3] = ffma2(w67.y, x23.y, acc[7][3]);
        }
        __syncthreads();
    }
    int t = mb * 2 + (tx >> 3);
    int bb = (tx & 7) * 8;
#pragma unroll
    for (int wn = 0; wn < 8; wn++) {
        int n = j0 + tw * 8 + wn;
        int g = n >> 8, u = n & 255;
        float bv = bias[n];
        uint64_t bd = pk2(bv, bv);
        uint64_t o0 = addx2(acc[wn][0], bd);
        uint64_t o1 = addx2(acc[wn][1], bd);
        uint64_t o2 = addx2(acc[wn][2], bd);
        uint64_t o3 = addx2(acc[wn][3], bd);
        float* op = &g_xg[(size_t)((t * 2 + dir) * 4 + g) * 16384 + u * 64 + bb];
        ulonglong2 s0; s0.x = o0; s0.y = o1;
        ulonglong2 s1; s1.x = o2; s1.y = o3;
        *(ulonglong2*)op = s0;
        *(ulonglong2*)(op + 4) = s1;
    }
}

// ---------------- kernel 4: persistent LSTM, per-quarter dataflow sync ----------------
// 128 blocks (dir = bx>>6, 4 units). 16 warps: kh = warp&3 (k quarter), bg = warp>>2.
// lane: uu = lane>>3 (unit), bp = lane&7 -> batches b0 = bg*16 + bp*2 (+1).
// Quarter q of h(t) is complete when the 16 blocks owning units [q*64, q*64+64) arrive
// on g_barQ[dir*4+q]. Warp kh waits only on its own quarter, then loads its private
// (quarter x 16-batch) 4KB slice into its own smem slab (no block-wide refill).
__global__ void __launch_bounds__(512, 1)
k_lstm_all(const float* __restrict__ Whf, const float* __restrict__ Whb) {
    extern __shared__ float sm[];
    uint64_t* wTd = (uint64_t*)sm;                      // 4096 u64 = 32KB [k][ug]
    uint64_t* hq  = (uint64_t*)(sm + 8192);             // 16 x 512 u64 = 64KB
    uint64_t* red = (uint64_t*)(sm + 8192 + 16384);     // 1536 u64 = 12KB

    int bx = blockIdx.x;
    int dir = bx >> 6;
    int u0 = (bx & 63) * 4;
    int myq = (bx & 63) >> 4;
    const float* W = dir ? Whb : Whf;
    int tid = threadIdx.x;
    int warp = tid >> 5, lane = tid & 31;
    int kh = warp & 3, bg = warp >> 2;
    int uu = lane >> 3, bp = lane & 7;
    int b0 = bg * 16 + bp * 2;

#pragma unroll
    for (int i = 0; i < 8; i++) {
        int idx = i * 512 + tid;
        int k = idx >> 4;
        int ug = idx & 15;
        int u2 = ug >> 2, g = ug & 3;
        float w = W[(size_t)(g * HH + u0 + u2) * HH + k];
        wTd[idx] = pk2(w, w);
    }
    __syncthreads();

    float c0 = 0.f, c1 = 0.f;
    uint64_t* slab = hq + (size_t)warp * 512;
    unsigned int* qc  = &g_barQ[dir * 4 + kh];        // this warp waits on it
    unsigned int* myc = &g_barQ[dir * 4 + myq];       // this block arrives on it
    uint64_t* redw = red + (size_t)((kh - 1) * 128 + bg * 32 + lane) * 4;
    uint64_t* redr = red + (size_t)(bg * 32 + lane) * 4;
    const uint64_t* wp0 = wTd + kh * 1024 + uu * 4;

    for (int s = 0; s < LL; s++) {
        int t = dir ? (LL - 1 - s) : s;

        uint64_t xgp[4];
        if (kh == 0) {
#pragma unroll
            for (int g = 0; g < 4; g++)
                xgp[g] = *(const uint64_t*)&g_xg[(size_t)((t * 2 + dir) * 4 + g) * 16384 + (u0 + uu) * 64 + b0];
        }

        uint64_t a0 = 0ull, a1 = 0ull, a2 = 0ull, a3 = 0ull;
        if (s > 0) {
            int tprev = dir ? (t + 1) : (t - 1);
            unsigned target = (unsigned)(s << 4);
            if (lane == 0) {
                unsigned v;
                while (1) {
                    asm volatile("ld.acquire.gpu.global.u32 %0, [%1];" : "=r"(v) : "l"(qc) : "memory");
                    if (v >= target) break;
                    __nanosleep(32);
                }
            }
            __syncwarp();
            // warp-private slice load: h[tprev][dir][kh*64 .. +64)[bg*16 .. +16)
            size_t hbase = (size_t)(tprev * 2 + dir) * 16384 + kh * 64 * 64 + bg * 16;
#pragma unroll
            for (int i = 0; i < 16; i++) {
                int gi = i * 32 + lane;          // 0..511
                int kk = gi >> 3, bj = gi & 7;
                slab[gi] = *(const uint64_t*)&g_hsT[hbase + kk * 64 + bj * 2];
            }
            __syncwarp();
            const uint64_t* wp = wp0;
            const uint64_t* hp = slab + bp;
#pragma unroll 8
            for (int kk = 0; kk < 64; kk++) {
                ulonglong2 wa = *(const ulonglong2*)wp;
                ulonglong2 wb = *(const ulonglong2*)(wp + 2);
                uint64_t hv = hp[kk * 8];
                a0 = ffma2(wa.x, hv, a0);
                a1 = ffma2(wa.y, hv, a1);
                a2 = ffma2(wb.x, hv, a2);
                a3 = ffma2(wb.y, hv, a3);
                wp += 16;
            }
        }
        if (kh != 0) {
            ulonglong2 s0; s0.x = a0; s0.y = a1;
            ulonglong2 s1; s1.x = a2; s1.y = a3;
            *(ulonglong2*)redw = s0;
            *(ulonglong2*)(redw + 2) = s1;
        }
        __syncthreads();
        if (kh == 0) {
#pragma unroll
            for (int j = 0; j < 3; j++) {
                const uint64_t* rp = redr + (size_t)j * 512;
                ulonglong2 r0 = *(const ulonglong2*)rp;
                ulonglong2 r1 = *(const ulonglong2*)(rp + 2);
                a0 = addx2(a0, r0.x); a1 = addx2(a1, r0.y);
                a2 = addx2(a2, r1.x); a3 = addx2(a3, r1.y);
            }
            float2 gi = up2(addx2(a0, xgp[0]));
            float2 gf = up2(addx2(a1, xgp[1]));
            float2 gg = up2(addx2(a2, xgp[2]));
            float2 go = up2(addx2(a3, xgp[3]));
            float si0 = 1.f / (1.f + expf(-gi.x));
            float sf0 = 1.f / (1.f + expf(-gf.x));
            float so0 = 1.f / (1.f + expf(-go.x));
            c0 = sf0 * c0 + si0 * tanhf(gg.x);
            float h0 = so0 * tanhf(c0);
            float si1 = 1.f / (1.f + expf(-gi.y));
            float sf1 = 1.f / (1.f + expf(-gf.y));
            float so1 = 1.f / (1.f + expf(-go.y));
            c1 = sf1 * c1 + si1 * tanhf(gg.y);
            float h1 = so1 * tanhf(c1);
            *(uint64_t*)&g_hsT[(size_t)(t * 2 + dir) * 16384 + (u0 + uu) * 64 + b0] = pk2(h0, h1);
        }
        if (s < LL - 1) {
            __syncthreads();     // all h stores done (cta fence); release below is cumulative
            if (tid == 0)
                asm volatile("red.release.gpu.global.add.u32 [%0], %1;" :: "l"(myc), "r"(1u) : "memory");
        }
    }
}

// ---------------- kernel 5: projection GEMM with dup'd B ----------------
__global__ void k_gemm2(const float* __restrict__ be, const float* __restrict__ ba) {
    __shared__ float Ash[16][64];
    __shared__ uint64_t Bsd[16 * 116];
    int t = blockIdx.x;
    const float* slabA = g_hsT + (size_t)t * 512 * 64;
    int tid = threadIdx.x;
    int tm = tid & 15, tn = tid >> 4;
    uint64_t acc2[2][7];
#pragma unroll
    for (int i = 0; i < 2; i++)
#pragma unroll
        for (int j = 0; j < 7; j++) acc2[i][j] = 0ull;
    for (int kt = 0; kt < 32; kt++) {
        int k0 = kt * 16;
        {
            int kk = tid >> 4, b4 = (tid & 15) * 4;
            *(float4*)&Ash[kk][b4] = *(const float4*)(slabA + (size_t)(k0 + kk) * 64 + b4);
        }
#pragma unroll
        for (int i = 0; i < 7; i++) {
            int idx = i * 256 + tid;
            int nn = idx >> 4, kk = idx & 15;
            float bv = g_Wcat[(size_t)nn * 512 + k0 + kk];
            Bsd[kk * 116 + nn] = pk2(bv, bv);
        }
        __syncthreads();
#pragma unroll
        for (int kk = 0; kk < 16; kk++) {
            ulonglong2 ap = *(const ulonglong2*)&Ash[kk][tm * 4];
#pragma unroll
            for (int j = 0; j < 7; j++) {
                uint64_t bd = Bsd[kk * 116 + tn * 7 + j];
                acc2[0][j] = ffma2(ap.x, bd, acc2[0][j]);
                acc2[1][j] = ffma2(ap.y, bd, acc2[1][j]);
            }
        }
        __syncthreads();
    }
#pragma unroll
    for (int j = 0; j < 7; j++) {
        int n = tn * 7 + j;
        float2 p0 = up2(acc2[0][j]);
        float2 p1 = up2(acc2[1][j]);
        float vv[4] = {p0.x, p0.y, p1.x, p1.y};
#pragma unroll
        for (int i = 0; i < 4; i++) {
            int m = t * 64 + tm * 4 + i;
            float v = vv[i];
            if (n < 34)       g_evbase[(size_t)m * NE + n]        = v + be[n];
            else if (n < 70)  g_base36[(size_t)m * NA + (n - 34)] = v + ba[n - 34];
            else if (n < 106) g_thadd [(size_t)m * NA + (n - 70)] = v;
        }
    }
}

// ---------------- kernel 6: event chains (prefetched) ----------------
__global__ void k_stageA(float* __restrict__ out_ev) {
    __shared__ float was[33 * 34];
    int tid = threadIdx.x;
    int b = tid >> 2, q = tid & 3;
    for (int i = tid; i < 33 * 34; i += 256) was[i] = g_WeGT[i];
    __syncthreads();
    int n0 = q * 9;
    int cnt = (q == 3) ? 7 : 9;
    float ctrg[9], cur[9];
#pragma unroll
    for (int i = 0; i < 9; i++) ctrg[i] = 0.f;
    {
        const float* eb = &g_evbase[(size_t)b * NE + n0];
#pragma unroll
        for (int i = 0; i < 9; i++) cur[i] = (i < cnt) ? eb[i] : -1e30f;
    }
    unsigned long long bits = 0ull;
    for (int t = 0; t < LL; t++) {
        float nxt[9];
        if (t < LL - 1) {
            const float* eb = &g_evbase[(size_t)((t + 1) * 64 + b) * NE + n0];
#pragma unroll
            for (int i = 0; i < 9; i++) if (i < cnt) nxt[i] = eb[i];
        }
        float o[9];
        float bestv = -1e30f;
        int besti = 1000;
#pragma unroll
        for (int i = 0; i < 9; i++) {
            if (i < cnt) {
                o[i] = cur[i] + ctrg[i];
                if (o[i] > bestv) { bestv = o[i]; besti = n0 + i; }
            }
        }
#pragma unroll
        for (int off = 1; off < 4; off <<= 1) {
            float ov = __shfl_xor_sync(0xffffffffu, bestv, off, 4);
            int   oi = __shfl_xor_sync(0xffffffffu, besti, off, 4);
            if (ov > bestv || (ov == bestv && oi < besti)) { bestv = ov; besti = oi; }
        }
        float* ob = &out_ev[((size_t)b * LL + t) * NE + n0];
#pragma unroll
        for (int i = 0; i < 9; i++) if (i < cnt) ob[i] = o[i];
        if (q == 0) g_emask[b * LL + t] = (besti > 0) ? 1 : 0;
        if (besti > 0) {
            int j = besti - 1;
            if (!((bits >> j) & 1ull)) {
                bits |= 1ull << j;
#pragma unroll
                for (int i = 0; i < 9; i++) if (i < cnt) ctrg[i] += was[j * NE + n0 + i];
            }
        }
#pragma unroll
        for (int i = 0; i < 9; i++) if (i < cnt) cur[i] = nxt[i];
    }
}

// ---------------- kernel 7: argument chains (prefetched) ----------------
__global__ void k_stageB(float* __restrict__ out_arg) {
    __shared__ float was[35 * 36];
    __shared__ unsigned char em[LL];
    int bx = blockIdx.x;
    int b = bx >> 1, ph = bx & 1;
    int tid = threadIdx.x;
    int p = tid >> 2;
    int pos = ph * 64 + p;
    int q = tid & 3;
    int n0 = q * 9;
    if (tid < LL) em[tid] = g_emask[b * LL + tid];
    for (int i = tid; i < 35 * 36; i += 256) was[i] = g_WaGT[i];
    __syncthreads();

    float base[9], C[9], thc[9];
    const float* bp = &g_base36[(size_t)(pos * 64 + b) * NA + n0];
#pragma unroll
    for (int i = 0; i < 9; i++) { base[i] = bp[i]; C[i] = 0.f; }
    {
        const float* th = &g_thadd[(size_t)b * NA + n0];
#pragma unroll
        for (int i = 0; i < 9; i++) thc[i] = th[i];
    }
    unsigned long long bits = 0ull;

    for (int t = 0; t < LL; t++) {
        float thn[9];
        if (t < LL - 1) {
            const float* th = &g_thadd[(size_t)((t + 1) * 64 + b) * NA + n0];
#pragma unroll
            for (int i = 0; i < 9; i++) thn[i] = th[i];
        }
        float o[9];
        float bestv = -1e30f;
        int besti = 1000;
#pragma unroll
        for (int i = 0; i < 9; i++) {
            o[i] = base[i] + C[i] + thc[i];
            if (o[i] > bestv) { bestv = o[i]; besti = n0 + i; }
        }
#pragma unroll
        for (int off = 1; off < 4; off <<= 1) {
            float ov = __shfl_xor_sync(0xffffffffu, bestv, off, 4);
            int   oi = __shfl_xor_sync(0xffffffffu, besti, off, 4);
            if (ov > bestv || (ov == bestv && oi < besti)) { bestv = ov; besti = oi; }
        }
        float* op = &out_arg[((size_t)(b * LL + t) * LL + pos) * NA + n0];
#pragma unroll
        for (int i = 0; i < 9; i++) op[i] = o[i];
        if (em[t] && besti > 0) {
            int j = besti - 1;
            if (!((bits >> j) & 1ull)) {
                bits |= 1ull << j;
#pragma unroll
                for (int i = 0; i < 9; i++) C[i] += was[j * NA + n0 + i];
            }
        }
#pragma unroll
        for (int i = 0; i < 9; i++) thc[i] = thn[i];
    }
}

// ---------------- launch ----------------
extern "C" void kernel_launch(void* const* d_in, const int* in_sizes, int n_in,
                              void* d_out, int out_size) {
    const int*   ids  = (const int*)  d_in[0];
    const float* emb  = (const float*)d_in[1];
    const float* Wihf = (const float*)d_in[2];
    const float* Whhf = (const float*)d_in[3];
    const float* bf   = (const float*)d_in[4];
    const float* Wihb = (const float*)d_in[5];
    const float* Whhb = (const float*)d_in[6];
    const float* bbv  = (const float*)d_in[7];
    const float* We   = (const float*)d_in[8];
    const float* be   = (const float*)d_in[9];
    const float* Wa   = (const float*)d_in[10];
    const float* ba   = (const float*)d_in[11];

    float* out_ev  = (float*)d_out;
    float* out_arg = out_ev + (size_t)BB * LL * NE;

    const int lstm_smem = 32768 + 65536 + 12288;   // 110592 B
    cudaFuncSetAttribute(k_lstm_all, cudaFuncAttributeMaxDynamicSharedMemorySize, lstm_smem);

    k_gather<<<LL, 256>>>(ids, emb);
    k_transW<<<dim3(32, 10, 2), dim3(32, 8)>>>(Wihf, Wihb);
    k_prep<<<64, 256>>>(We, Wa);
    k_gemm1<<<dim3(16, 64), 256>>>(bf, bbv);
    k_lstm_all<<<128, 512, lstm_smem>>>(Whhf, Whhb);
    k_gemm2<<<128, 256>>>(be, ba);
    k_stageA<<<1, 256>>>(out_ev);
    k_stageB<<<128, 256>>>(out_arg);
}

// round 8
// speedup vs baseline: 1.8174x; 1.8174x over previous
#include <cuda_runtime.h>
#include <math.h>
#include <stdint.h>

static constexpr int BB   = 64;
static constexpr int LL   = 128;
static constexpr int EMBD = 300;
static constexpr int HH   = 256;
static constexpr int NE   = 34;
static constexpr int NA   = 36;

// ---------------- scratch ----------------
__device__ float g_xT  [300 * 8192];              // [e][m=t*64+b]
__device__ float g_WT  [2 * 300 * 1024];          // [dir][k][row]
__device__ float g_xg  [LL * 2 * 4 * HH * BB];    // [t][dir][g][u][b]
__device__ float g_hsT [LL * 2 * HH * BB];        // [t][dir][u][b]
__device__ float g_evbase[LL * BB * NE];          // [t*64+b][34]
__device__ float g_base36[LL * BB * NA];          // [pos*64+b][36]
__device__ float g_thadd [LL * BB * NA];          // [t*64+b][36]
__device__ float g_Wcat [112 * 512];
__device__ float g_WeGT [33 * 34];
__device__ float g_WaGT [35 * 36];
__device__ unsigned char g_emask[BB * LL];
__device__ unsigned int g_barQ[8];                // [dir][batch-slice]

// ---------------- f32x2 helpers ----------------
__device__ __forceinline__ uint64_t pk2(float x, float y) {
    uint64_t r; asm("mov.b64 %0,{%1,%2};" : "=l"(r) : "f"(x), "f"(y)); return r;
}
__device__ __forceinline__ uint64_t ffma2(uint64_t a, uint64_t b, uint64_t c) {
    uint64_t d; asm("fma.rn.f32x2 %0,%1,%2,%3;" : "=l"(d) : "l"(a), "l"(b), "l"(c)); return d;
}
__device__ __forceinline__ uint64_t addx2(uint64_t a, uint64_t b) {
    uint64_t d; asm("add.rn.f32x2 %0,%1,%2;" : "=l"(d) : "l"(a), "l"(b)); return d;
}
__device__ __forceinline__ float2 up2(uint64_t v) {
    float2 r; asm("mov.b64 {%0,%1},%2;" : "=f"(r.x), "=f"(r.y) : "l"(v)); return r;
}

// ---------------- kernel 1: embedding gather (transposed out) ----------------
__global__ void k_gather(const int* __restrict__ ids, const float* __restrict__ emb) {
    int t = blockIdx.x;
    int tid = threadIdx.x;
    int b = tid >> 2, q = tid & 3;
    int id = ids[b * LL + t];
    const float4* src = (const float4*)(emb + (size_t)id * EMBD);
#pragma unroll
    for (int j = 0; j < 19; j++) {
        int e4 = q + j * 4;
        if (e4 < 75) {
            float4 v = src[e4];
            int e = e4 * 4;
            size_t base = (size_t)e * 8192 + t * 64 + b;
            g_xT[base]          = v.x;
            g_xT[base + 8192]   = v.y;
            g_xT[base + 16384]  = v.z;
            g_xT[base + 24576]  = v.w;
        }
    }
}

// ---------------- kernel 1b: transpose W_ih (both dirs) ----------------
__global__ void k_transW(const float* __restrict__ Wf, const float* __restrict__ Wb) {
    __shared__ float ts[32][33];
    const float* W = blockIdx.z ? Wb : Wf;
    float* out = g_WT + (size_t)blockIdx.z * 300 * 1024;
    int n0 = blockIdx.x * 32, k0 = blockIdx.y * 32;
    int tx = threadIdx.x, ty = threadIdx.y;
#pragma unroll
    for (int r = 0; r < 4; r++) {
        int row = ty + r * 8;
        int k = k0 + tx;
        if (k < 300) ts[row][tx] = W[(size_t)(n0 + row) * 300 + k];
    }
    __syncthreads();
#pragma unroll
    for (int r = 0; r < 4; r++) {
        int row = ty + r * 8;
        int k = k0 + row;
        if (k < 300) out[(size_t)k * 1024 + n0 + tx] = ts[tx][row];
    }
}

// ---------------- kernel 2: pack decode weights + reset counters ----------------
__global__ void k_prep(const float* __restrict__ We, const float* __restrict__ Wa) {
    if (blockIdx.x == 0 && threadIdx.x < 8) g_barQ[threadIdx.x] = 0u;
    int tid = blockIdx.x * blockDim.x + threadIdx.x;
    int stride = gridDim.x * blockDim.x;
    for (int i = tid; i < 112 * 512; i += stride) {
        int n = i >> 9, k = i & 511;
        float v = 0.f;
        if (n < 34)       v = We[n * 545 + k];
        else if (n < 70)  v = Wa[(n - 34) * 1059 + k];
        else if (n < 106) v = Wa[(n - 70) * 1059 + 512 + k];
        g_Wcat[i] = v;
    }
    for (int i = tid; i < 33 * 34; i += stride) {
        int j = i / 34, e = i % 34;
        g_WeGT[i] = We[e * 545 + 512 + j];
    }
    for (int i = tid; i < 35 * 36; i += stride) {
        int j = i / 36, e = i % 36;
        g_WaGT[i] = Wa[e * 1059 + 1024 + j];
    }
}

// ---------------- kernel 3: input GEMM (R6 form: scalar smem + reg-dup) ----------------
__global__ void k_gemm1(const float* __restrict__ bf, const float* __restrict__ bbv) {
    __shared__ float Xs[30 * 128];
    __shared__ float Ws[30 * 128];
    int nb = blockIdx.x;
    int mb = blockIdx.y;
    int dir = nb >> 3;
    int j0 = (nb & 7) * 128;
    int m0 = mb * 128;
    const float* WT = g_WT + (size_t)dir * 300 * 1024;
    const float* bias = dir ? bbv : bf;
    int tid = threadIdx.x;
    int tw = tid & 15, tx = tid >> 4;
    uint64_t acc[8][4];
#pragma unroll
    for (int i = 0; i < 8; i++)
#pragma unroll
        for (int j = 0; j < 4; j++) acc[i][j] = 0ull;

    for (int kt = 0; kt < 10; kt++) {
        int k0 = kt * 30;
#pragma unroll
        for (int i = 0; i < 15; i++) {
            int idx = i * 256 + tid;
            int kk = idx >> 7, mm = idx & 127;
            Xs[idx] = g_xT[(size_t)(k0 + kk) * 8192 + m0 + mm];
            Ws[idx] = WT[(size_t)(k0 + kk) * 1024 + j0 + mm];
        }
        __syncthreads();
#pragma unroll 5
        for (int kk = 0; kk < 30; kk++) {
            float4 w0 = *(const float4*)&Ws[kk * 128 + tw * 8];
            float4 w1 = *(const float4*)&Ws[kk * 128 + tw * 8 + 4];
            ulonglong2 x01 = *(const ulonglong2*)&Xs[kk * 128 + tx * 8];
            ulonglong2 x23 = *(const ulonglong2*)&Xs[kk * 128 + tx * 8 + 4];
            uint64_t wd[8];
            wd[0] = pk2(w0.x, w0.x); wd[1] = pk2(w0.y, w0.y);
            wd[2] = pk2(w0.z, w0.z); wd[3] = pk2(w0.w, w0.w);
            wd[4] = pk2(w1.x, w1.x); wd[5] = pk2(w1.y, w1.y);
            wd[6] = pk2(w1.z, w1.z); wd[7] = pk2(w1.w, w1.w);
#pragma unroll
            for (int wn = 0; wn < 8; wn++) {
                acc[wn][0] = ffma2(wd[wn], x01.x, acc[wn][0]);
                acc[wn][1] = ffma2(wd[wn], x01.y, acc[wn][1]);
                acc[wn][2] = ffma2(wd[wn], x23.x, acc[wn][2]);
                acc[wn][3] = ffma2(wd[wn], x23.y, acc[wn][3]);
            }
        }
        __syncthreads();
    }
    int t = mb * 2 + (tx >> 3);
    int bb = (tx & 7) * 8;
#pragma unroll
    for (int wn = 0; wn < 8; wn++) {
        int n = j0 + tw * 8 + wn;
        int g = n >> 8, u = n & 255;
        float bv = bias[n];
        uint64_t bd = pk2(bv, bv);
        uint64_t o0 = addx2(acc[wn][0], bd);
        uint64_t o1 = addx2(acc[wn][1], bd);
        uint64_t o2 = addx2(acc[wn][2], bd);
        uint64_t o3 = addx2(acc[wn][3], bd);
        float* op = &g_xg[(size_t)((t * 2 + dir) * 4 + g) * 16384 + u * 64 + bb];
        ulonglong2 s0; s0.x = o0; s0.y = o1;
        ulonglong2 s1; s1.x = o2; s1.y = o3;
        *(ulonglong2*)op = s0;
        *(ulonglong2*)(op + 4) = s1;
    }
}

// ---------------- kernel 4: persistent LSTM, (16-unit x 16-batch) blocks ----------------
// 128 blocks: dir = bx>>6, r = bx&63, uslice = r&15 (u0 = uslice*16),
// bslice = r>>4 (batches bg0 = bslice*16). Sync group = (dir, bslice): 16 blocks,
// counter g_barQ[dir*4 + bslice]. Per-step h refill = 16 KB (own batches only).
// Thread = (uu = tid>>4, bl = tid&15): all 4 gates of (u0+uu, bg0+bl).
// Weights pre-paired in smem: wp[0][uu][k] = (Wi,Wf), wp[1][uu][k] = (Wg,Wo).
__global__ void __launch_bounds__(256, 1)
k_lstm_all(const float* __restrict__ Whf, const float* __restrict__ Whb) {
    extern __shared__ float sm[];
    uint64_t* wp = (uint64_t*)sm;            // 8192 u64 = 64 KB: [pair][uu][k]
    float* hsm = sm + 16384;                 // [bl][258] = 16512 B

    int bx = blockIdx.x;
    int dir = bx >> 6;
    int r = bx & 63;
    int u0 = (r & 15) * 16;
    int bg0 = (r >> 4) * 16;
    const float* W = dir ? Whb : Whf;
    int tid = threadIdx.x;
    int uu = tid >> 4, bl = tid & 15;
    int u = u0 + uu;
    int bglob = bg0 + bl;

    // pack weights once: wp[pair*4096 + uq*256 + k]
#pragma unroll
    for (int i = 0; i < 32; i++) {
        int idx = i * 256 + tid;
        int pair = idx >> 12;
        int uq = (idx >> 8) & 15;
        int k = idx & 255;
        float a = W[(size_t)((pair * 2 + 0) * HH + u0 + uq) * HH + k];
        float b = W[(size_t)((pair * 2 + 1) * HH + u0 + uq) * HH + k];
        wp[idx] = pk2(a, b);
    }
    __syncthreads();

    float c = 0.f;
    unsigned int* ctr = &g_barQ[dir * 4 + (r >> 4)];
    const uint64_t* w0p = wp + uu * 256;
    const uint64_t* w1p = wp + 4096 + uu * 256;
    const float* hrow = hsm + bl * 258;

    for (int s = 0; s < LL; s++) {
        int t = dir ? (LL - 1 - s) : s;

        // xg gates for this (t, dir, u, bglob)
        size_t xb = (size_t)(t * 2 + dir) * 4 * 16384 + (size_t)u * 64 + bglob;
        float xi = g_xg[xb];
        float xf = g_xg[xb + 16384];
        float xgg = g_xg[xb + 2 * 16384];
        float xo = g_xg[xb + 3 * 16384];

        float vi = xi, vf = xf, vg = xgg, vo = xo;
        if (s > 0) {
            int tprev = dir ? (t + 1) : (t - 1);
            if (tid == 0) {
                unsigned target = (unsigned)(s * 16);
                unsigned v;
                while (1) {
                    asm volatile("ld.acquire.gpu.global.u32 %0, [%1];" : "=r"(v) : "l"(ctr) : "memory");
                    if (v >= target) break;
                    __nanosleep(32);
                }
            }
            __syncthreads();
            // refill: h(t-1)[dir][all 256 u][bg0..bg0+15] -> hsm[bl][k]
            size_t hbase = (size_t)(tprev * 2 + dir) * 16384 + bg0;
#pragma unroll
            for (int i = 0; i < 16; i++) {
                int gi = i * 256 + tid;          // 0..4095
                int ku = gi >> 4;                // unit index = k
                int bb = gi & 15;
                hsm[bb * 258 + ku] = g_hsT[hbase + (size_t)ku * 64 + bb];
            }
            __syncthreads();

            uint64_t a01 = 0ull, a23 = 0ull;
#pragma unroll 8
            for (int k = 0; k < HH; k += 2) {
                ulonglong2 wA = *(const ulonglong2*)(w0p + k);
                ulonglong2 wB = *(const ulonglong2*)(w1p + k);
                float2 h2 = *(const float2*)(hrow + k);
                uint64_t hd0 = pk2(h2.x, h2.x);
                uint64_t hd1 = pk2(h2.y, h2.y);
                a01 = ffma2(wA.x, hd0, a01);
                a23 = ffma2(wB.x, hd0, a23);
                a01 = ffma2(wA.y, hd1, a01);
                a23 = ffma2(wB.y, hd1, a23);
            }
            float2 v01 = up2(a01);
            float2 v23 = up2(a23);
            vi += v01.x; vf += v01.y; vg += v23.x; vo += v23.y;
        }

        float si = 1.f / (1.f + expf(-vi));
        float sf = 1.f / (1.f + expf(-vf));
        float so = 1.f / (1.f + expf(-vo));
        c = sf * c + si * tanhf(vg);
        float h = so * tanhf(c);
        g_hsT[(size_t)(t * 2 + dir) * 16384 + (size_t)u * 64 + bglob] = h;

        if (s < LL - 1) {
            __syncthreads();   // all h stores + hsm reads done before release / next refill
            if (tid == 0)
                asm volatile("red.release.gpu.global.add.u32 [%0], %1;" :: "l"(ctr), "r"(1u) : "memory");
        }
    }
}

// ---------------- kernel 5: projection GEMM  hs[8192,512] @ Wcat^T (R6 form) ----------------
__global__ void k_gemm2(const float* __restrict__ be, const float* __restrict__ ba) {
    __shared__ float Ash[16][64];
    __shared__ float Bsh[16][116];
    int t = blockIdx.x;
    const float* slabA = g_hsT + (size_t)t * 512 * 64;
    int tid = threadIdx.x;
    int tm = tid & 15, tn = tid >> 4;
    float acc[4][7] = {};
    for (int kt = 0; kt < 32; kt++) {
        int k0 = kt * 16;
        {
            int kk = tid >> 4, b4 = (tid & 15) * 4;
            *(float4*)&Ash[kk][b4] = *(const float4*)(slabA + (size_t)(k0 + kk) * 64 + b4);
        }
#pragma unroll
        for (int i = 0; i < 7; i++) {
            int idx = i * 256 + tid;
            int nn = idx >> 4, kk = idx & 15;
            Bsh[kk][nn] = g_Wcat[(size_t)nn * 512 + k0 + kk];
        }
        __syncthreads();
#pragma unroll
        for (int kk = 0; kk < 16; kk++) {
            float4 a = *(float4*)&Ash[kk][tm * 4];
#pragma unroll
            for (int j = 0; j < 7; j++) {
                float bv = Bsh[kk][tn * 7 + j];
                acc[0][j] += a.x * bv;
                acc[1][j] += a.y * bv;
                acc[2][j] += a.z * bv;
                acc[3][j] += a.w * bv;
            }
        }
        __syncthreads();
    }
#pragma unroll
    for (int i = 0; i < 4; i++) {
        int m = t * 64 + tm * 4 + i;
#pragma unroll
        for (int j = 0; j < 7; j++) {
            int n = tn * 7 + j;
            float v = acc[i][j];
            if (n < 34)       g_evbase[(size_t)m * NE + n]        = v + be[n];
            else if (n < 70)  g_base36[(size_t)m * NA + (n - 34)] = v + ba[n - 34];
            else if (n < 106) g_thadd [(size_t)m * NA + (n - 70)] = v;
        }
    }
}

// ---------------- kernel 6: event chains (R6 form) ----------------
__global__ void k_stageA(float* __restrict__ out_ev) {
    __shared__ float was[33 * 34];
    int tid = threadIdx.x;
    int b = tid >> 2, q = tid & 3;
    for (int i = tid; i < 33 * 34; i += 256) was[i] = g_WeGT[i];
    __syncthreads();
    int n0 = q * 9;
    int cnt = (q == 3) ? 7 : 9;
    float ctrg[9];
#pragma unroll
    for (int i = 0; i < 9; i++) ctrg[i] = 0.f;
    unsigned long long bits = 0ull;
    for (int t = 0; t < LL; t++) {
        const float* eb = &g_evbase[(size_t)(t * 64 + b) * NE + n0];
        float o[9];
        float bestv = -1e30f;
        int besti = 1000;
#pragma unroll
        for (int i = 0; i < 9; i++) {
            if (i < cnt) {
                o[i] = eb[i] + ctrg[i];
                if (o[i] > bestv) { bestv = o[i]; besti = n0 + i; }
            }
        }
#pragma unroll
        for (int off = 1; off < 4; off <<= 1) {
            float ov = __shfl_xor_sync(0xffffffffu, bestv, off, 4);
            int   oi = __shfl_xor_sync(0xffffffffu, besti, off, 4);
            if (ov > bestv || (ov == bestv && oi < besti)) { bestv = ov; besti = oi; }
        }
        float* ob = &out_ev[((size_t)b * LL + t) * NE + n0];
#pragma unroll
        for (int i = 0; i < 9; i++) if (i < cnt) ob[i] = o[i];
        if (q == 0) g_emask[b * LL + t] = (besti > 0) ? 1 : 0;
        if (besti > 0) {
            int j = besti - 1;
            if (!((bits >> j) & 1ull)) {
                bits |= 1ull << j;
#pragma unroll
                for (int i = 0; i < 9; i++) if (i < cnt) ctrg[i] += was[j * NE + n0 + i];
            }
        }
    }
}

// ---------------- kernel 7: argument chains (R6 form) ----------------
__global__ void k_stageB(float* __restrict__ out_arg) {
    __shared__ float was[35 * 36];
    __shared__ unsigned char em[LL];
    int bx = blockIdx.x;
    int b = bx >> 1, ph = bx & 1;
    int tid = threadIdx.x;
    int p = tid >> 2;
    int pos = ph * 64 + p;
    int q = tid & 3;
    int n0 = q * 9;
    if (tid < LL) em[tid] = g_emask[b * LL + tid];
    for (int i = tid; i < 35 * 36; i += 256) was[i] = g_WaGT[i];
    __syncthreads();

    float base[9], C[9];
    const float* bp = &g_base36[(size_t)(pos * 64 + b) * NA + n0];
#pragma unroll
    for (int i = 0; i < 9; i++) { base[i] = bp[i]; C[i] = 0.f; }
    unsigned long long bits = 0ull;

    for (int t = 0; t < LL; t++) {
        const float* th = &g_thadd[(size_t)(t * 64 + b) * NA + n0];
        float o[9];
        float bestv = -1e30f;
        int besti = 1000;
#pragma unroll
        for (int i = 0; i < 9; i++) {
            o[i] = base[i] + C[i] + th[i];
            if (o[i] > bestv) { bestv = o[i]; besti = n0 + i; }
        }
#pragma unroll
        for (int off = 1; off < 4; off <<= 1) {
            float ov = __shfl_xor_sync(0xffffffffu, bestv, off, 4);
            int   oi = __shfl_xor_sync(0xffffffffu, besti, off, 4);
            if (ov > bestv || (ov == bestv && oi < besti)) { bestv = ov; besti = oi; }
        }
        float* op = &out_arg[((size_t)(b * LL + t) * LL + pos) * NA + n0];
#pragma unroll
        for (int i = 0; i < 9; i++) op[i] = o[i];
        if (em[t] && besti > 0) {
            int j = besti - 1;
            if (!((bits >> j) & 1ull)) {
                bits |= 1ull << j;
#pragma unroll
                for (int i = 0; i < 9; i++) C[i] += was[j * NA + n0 + i];
            }
        }
    }
}

// ---------------- launch ----------------
extern "C" void kernel_launch(void* const* d_in, const int* in_sizes, int n_in,
                              void* d_out, int out_size) {
    const int*   ids  = (const int*)  d_in[0];
    const float* emb  = (const float*)d_in[1];
    const float* Wihf = (const float*)d_in[2];
    const float* Whhf = (const float*)d_in[3];
    const float* bf   = (const float*)d_in[4];
    const float* Wihb = (const float*)d_in[5];
    const float* Whhb = (const float*)d_in[6];
    const float* bbv  = (const float*)d_in[7];
    const float* We   = (const float*)d_in[8];
    const float* be   = (const float*)d_in[9];
    const float* Wa   = (const float*)d_in[10];
    const float* ba   = (const float*)d_in[11];

    float* out_ev  = (float*)d_out;
    float* out_arg = out_ev + (size_t)BB * LL * NE;

    const int lstm_smem = 65536 + 16 * 258 * 4;   // 82048 B
    cudaFuncSetAttribute(k_lstm_all, cudaFuncAttributeMaxDynamicSharedMemorySize, lstm_smem);

    k_gather<<<LL, 256>>>(ids, emb);
    k_transW<<<dim3(32, 10, 2), dim3(32, 8)>>>(Wihf, Wihb);
    k_prep<<<64, 256>>>(We, Wa);
    k_gemm1<<<dim3(16, 64), 256>>>(bf, bbv);
    k_lstm_all<<<128, 256, lstm_smem>>>(Whhf, Whhb);
    k_gemm2<<<128, 256>>>(be, ba);
    k_stageA<<<1, 256>>>(out_ev);
    k_stageB<<<128, 256>>>(out_arg);
}

// round 9
// speedup vs baseline: 2.0658x; 1.1367x over previous
#include <cuda_runtime.h>
#include <math.h>
#include <stdint.h>

static constexpr int BB   = 64;
static constexpr int LL   = 128;
static constexpr int EMBD = 300;
static constexpr int HH   = 256;
static constexpr int NE   = 34;
static constexpr int NA   = 36;

// ---------------- scratch ----------------
__device__ float g_xT  [300 * 8192];              // [e][m=t*64+b]
__device__ float g_WT  [2 * 300 * 1024];          // [dir][k][row]
__device__ float g_xg  [LL * 2 * 4 * HH * BB];    // [t][dir][g][u][b]
__device__ float g_hsT [LL * 2 * HH * BB];        // [t][dir][u][b]
__device__ float g_evbase[LL * BB * NE];          // [t*64+b][34]
__device__ float g_base36[LL * BB * NA];          // [pos*64+b][36]
__device__ float g_thadd [LL * BB * NA];          // [t*64+b][36]
__device__ float g_Wcat [112 * 512];
__device__ float g_WeGT [33 * 34];
__device__ float g_WaGT [35 * 36];
__device__ unsigned char g_emask[BB * LL];
__device__ unsigned int g_barQ[8];                // [dir][batch-slice]

// ---------------- f32x2 helpers ----------------
__device__ __forceinline__ uint64_t pk2(float x, float y) {
    uint64_t r; asm("mov.b64 %0,{%1,%2};" : "=l"(r) : "f"(x), "f"(y)); return r;
}
__device__ __forceinline__ uint64_t ffma2(uint64_t a, uint64_t b, uint64_t c) {
    uint64_t d; asm("fma.rn.f32x2 %0,%1,%2,%3;" : "=l"(d) : "l"(a), "l"(b), "l"(c)); return d;
}
__device__ __forceinline__ uint64_t addx2(uint64_t a, uint64_t b) {
    uint64_t d; asm("add.rn.f32x2 %0,%1,%2;" : "=l"(d) : "l"(a), "l"(b)); return d;
}
__device__ __forceinline__ float2 up2(uint64_t v) {
    float2 r; asm("mov.b64 {%0,%1},%2;" : "=f"(r.x), "=f"(r.y) : "l"(v)); return r;
}

// ---------------- kernel 1 (fused): gather | transW | pack decode weights ----------------
// blocks [0,128)   : embedding gather (t = bid)
// blocks [128,768) : W_ih transpose (640 tiles)
// blocks [768,832) : decode-weight packing + barrier reset
__global__ void k_prep_all(const int* __restrict__ ids, const float* __restrict__ emb,
                           const float* __restrict__ Wf, const float* __restrict__ Wb,
                           const float* __restrict__ We, const float* __restrict__ Wa) {
    __shared__ float ts[32][33];
    int bid = blockIdx.x;
    int tid = threadIdx.x;

    if (bid < 128) {
        int t = bid;
        int b = tid >> 2, q = tid & 3;
        int id = ids[b * LL + t];
        const float4* src = (const float4*)(emb + (size_t)id * EMBD);
#pragma unroll
        for (int j = 0; j < 19; j++) {
            int e4 = q + j * 4;
            if (e4 < 75) {
                float4 v = src[e4];
                int e = e4 * 4;
                size_t base = (size_t)e * 8192 + t * 64 + b;
                g_xT[base]          = v.x;
                g_xT[base + 8192]   = v.y;
                g_xT[base + 16384]  = v.z;
                g_xT[base + 24576]  = v.w;
            }
        }
    } else if (bid < 768) {
        int r3 = bid - 128;                 // 640 = 32 x 10 x 2
        int z = r3 / 320;
        int rem = r3 % 320;
        int bxx = rem & 31;                 // 32 n-tiles
        int byy = rem >> 5;                 // 10 k-tiles
        const float* W = z ? Wb : Wf;
        float* out = g_WT + (size_t)z * 300 * 1024;
        int n0 = bxx * 32, k0 = byy * 32;
        int tx = tid & 31, ty = tid >> 5;   // 32 x 8
#pragma unroll
        for (int r = 0; r < 4; r++) {
            int row = ty + r * 8;
            int k = k0 + tx;
            if (k < 300) ts[row][tx] = W[(size_t)(n0 + row) * 300 + k];
        }
        __syncthreads();
#pragma unroll
        for (int r = 0; r < 4; r++) {
            int row = ty + r * 8;
            int k = k0 + row;
            if (k < 300) out[(size_t)k * 1024 + n0 + tx] = ts[tx][row];
        }
    } else {
        int pb = bid - 768;                 // 64 blocks
        if (pb == 0 && tid < 8) g_barQ[tid] = 0u;
        int gt = pb * 256 + tid;
        int stride = 64 * 256;
        for (int i = gt; i < 112 * 512; i += stride) {
            int n = i >> 9, k = i & 511;
            float v = 0.f;
            if (n < 34)       v = We[n * 545 + k];
            else if (n < 70)  v = Wa[(n - 34) * 1059 + k];
            else if (n < 106) v = Wa[(n - 70) * 1059 + 512 + k];
            g_Wcat[i] = v;
        }
        for (int i = gt; i < 33 * 34; i += stride) {
            int j = i / 34, e = i % 34;
            g_WeGT[i] = We[e * 545 + 512 + j];
        }
        for (int i = gt; i < 35 * 36; i += stride) {
            int j = i / 36, e = i % 36;
            g_WaGT[i] = Wa[e * 1059 + 1024 + j];
        }
    }
}

// ---------------- kernel 2: input GEMM (R6/R8 form) ----------------
__global__ void k_gemm1(const float* __restrict__ bf, const float* __restrict__ bbv) {
    __shared__ float Xs[30 * 128];
    __shared__ float Ws[30 * 128];
    int nb = blockIdx.x;
    int mb = blockIdx.y;
    int dir = nb >> 3;
    int j0 = (nb & 7) * 128;
    int m0 = mb * 128;
    const float* WT = g_WT + (size_t)dir * 300 * 1024;
    const float* bias = dir ? bbv : bf;
    int tid = threadIdx.x;
    int tw = tid & 15, tx = tid >> 4;
    uint64_t acc[8][4];
#pragma unroll
    for (int i = 0; i < 8; i++)
#pragma unroll
        for (int j = 0; j < 4; j++) acc[i][j] = 0ull;

    for (int kt = 0; kt < 10; kt++) {
        int k0 = kt * 30;
#pragma unroll
        for (int i = 0; i < 15; i++) {
            int idx = i * 256 + tid;
            int kk = idx >> 7, mm = idx & 127;
            Xs[idx] = g_xT[(size_t)(k0 + kk) * 8192 + m0 + mm];
            Ws[idx] = WT[(size_t)(k0 + kk) * 1024 + j0 + mm];
        }
        __syncthreads();
#pragma unroll 5
        for (int kk = 0; kk < 30; kk++) {
            float4 w0 = *(const float4*)&Ws[kk * 128 + tw * 8];
            float4 w1 = *(const float4*)&Ws[kk * 128 + tw * 8 + 4];
            ulonglong2 x01 = *(const ulonglong2*)&Xs[kk * 128 + tx * 8];
            ulonglong2 x23 = *(const ulonglong2*)&Xs[kk * 128 + tx * 8 + 4];
            uint64_t wd[8];
            wd[0] = pk2(w0.x, w0.x); wd[1] = pk2(w0.y, w0.y);
            wd[2] = pk2(w0.z, w0.z); wd[3] = pk2(w0.w, w0.w);
            wd[4] = pk2(w1.x, w1.x); wd[5] = pk2(w1.y, w1.y);
            wd[6] = pk2(w1.z, w1.z); wd[7] = pk2(w1.w, w1.w);
#pragma unroll
            for (int wn = 0; wn < 8; wn++) {
                acc[wn][0] = ffma2(wd[wn], x01.x, acc[wn][0]);
                acc[wn][1] = ffma2(wd[wn], x01.y, acc[wn][1]);
                acc[wn][2] = ffma2(wd[wn], x23.x, acc[wn][2]);
                acc[wn][3] = ffma2(wd[wn], x23.y, acc[wn][3]);
            }
        }
        __syncthreads();
    }
    int t = mb * 2 + (tx >> 3);
    int bb = (tx & 7) * 8;
#pragma unroll
    for (int wn = 0; wn < 8; wn++) {
        int n = j0 + tw * 8 + wn;
        int g = n >> 8, u = n & 255;
        float bv = bias[n];
        uint64_t bd = pk2(bv, bv);
        uint64_t o0 = addx2(acc[wn][0], bd);
        uint64_t o1 = addx2(acc[wn][1], bd);
        uint64_t o2 = addx2(acc[wn][2], bd);
        uint64_t o3 = addx2(acc[wn][3], bd);
        float* op = &g_xg[(size_t)((t * 2 + dir) * 4 + g) * 16384 + u * 64 + bb];
        ulonglong2 s0; s0.x = o0; s0.y = o1;
        ulonglong2 s1; s1.x = o2; s1.y = o3;
        *(ulonglong2*)op = s0;
        *(ulonglong2*)(op + 4) = s1;
    }
}

// ---------------- kernel 3: persistent LSTM (R8 form, unchanged) ----------------
__global__ void __launch_bounds__(256, 1)
k_lstm_all(const float* __restrict__ Whf, const float* __restrict__ Whb) {
    extern __shared__ float sm[];
    uint64_t* wp = (uint64_t*)sm;            // 8192 u64 = 64 KB: [pair][uu][k]
    float* hsm = sm + 16384;                 // [bl][258]

    int bx = blockIdx.x;
    int dir = bx >> 6;
    int r = bx & 63;
    int u0 = (r & 15) * 16;
    int bg0 = (r >> 4) * 16;
    const float* W = dir ? Whb : Whf;
    int tid = threadIdx.x;
    int uu = tid >> 4, bl = tid & 15;
    int u = u0 + uu;
    int bglob = bg0 + bl;

#pragma unroll
    for (int i = 0; i < 32; i++) {
        int idx = i * 256 + tid;
        int pair = idx >> 12;
        int uq = (idx >> 8) & 15;
        int k = idx & 255;
        float a = W[(size_t)((pair * 2 + 0) * HH + u0 + uq) * HH + k];
        float b = W[(size_t)((pair * 2 + 1) * HH + u0 + uq) * HH + k];
        wp[idx] = pk2(a, b);
    }
    __syncthreads();

    float c = 0.f;
    unsigned int* ctr = &g_barQ[dir * 4 + (r >> 4)];
    const uint64_t* w0p = wp + uu * 256;
    const uint64_t* w1p = wp + 4096 + uu * 256;
    const float* hrow = hsm + bl * 258;

    for (int s = 0; s < LL; s++) {
        int t = dir ? (LL - 1 - s) : s;

        size_t xb = (size_t)(t * 2 + dir) * 4 * 16384 + (size_t)u * 64 + bglob;
        float vi = g_xg[xb];
        float vf = g_xg[xb + 16384];
        float vg = g_xg[xb + 2 * 16384];
        float vo = g_xg[xb + 3 * 16384];

        if (s > 0) {
            int tprev = dir ? (t + 1) : (t - 1);
            if (tid == 0) {
                unsigned target = (unsigned)(s * 16);
                unsigned v;
                while (1) {
                    asm volatile("ld.acquire.gpu.global.u32 %0, [%1];" : "=r"(v) : "l"(ctr) : "memory");
                    if (v >= target) break;
                    __nanosleep(32);
                }
            }
            __syncthreads();
            size_t hbase = (size_t)(tprev * 2 + dir) * 16384 + bg0;
#pragma unroll
            for (int i = 0; i < 16; i++) {
                int gi = i * 256 + tid;
                int ku = gi >> 4;
                int bb = gi & 15;
                hsm[bb * 258 + ku] = g_hsT[hbase + (size_t)ku * 64 + bb];
            }
            __syncthreads();

            uint64_t a01 = 0ull, a23 = 0ull;
#pragma unroll 8
            for (int k = 0; k < HH; k += 2) {
                ulonglong2 wA = *(const ulonglong2*)(w0p + k);
                ulonglong2 wB = *(const ulonglong2*)(w1p + k);
                float2 h2 = *(const float2*)(hrow + k);
                uint64_t hd0 = pk2(h2.x, h2.x);
                uint64_t hd1 = pk2(h2.y, h2.y);
                a01 = ffma2(wA.x, hd0, a01);
                a23 = ffma2(wB.x, hd0, a23);
                a01 = ffma2(wA.y, hd1, a01);
                a23 = ffma2(wB.y, hd1, a23);
            }
            float2 v01 = up2(a01);
            float2 v23 = up2(a23);
            vi += v01.x; vf += v01.y; vg += v23.x; vo += v23.y;
        }

        float si = 1.f / (1.f + expf(-vi));
        float sf = 1.f / (1.f + expf(-vf));
        float so = 1.f / (1.f + expf(-vo));
        c = sf * c + si * tanhf(vg);
        float h = so * tanhf(c);
        g_hsT[(size_t)(t * 2 + dir) * 16384 + (size_t)u * 64 + bglob] = h;

        if (s < LL - 1) {
            __syncthreads();
            if (tid == 0)
                asm volatile("red.release.gpu.global.add.u32 [%0], %1;" :: "l"(ctr), "r"(1u) : "memory");
        }
    }
}

// ---------------- kernel 4: projection GEMM (R8 form) ----------------
__global__ void k_gemm2(const float* __restrict__ be, const float* __restrict__ ba) {
    __shared__ float Ash[16][64];
    __shared__ float Bsh[16][116];
    int t = blockIdx.x;
    const float* slabA = g_hsT + (size_t)t * 512 * 64;
    int tid = threadIdx.x;
    int tm = tid & 15, tn = tid >> 4;
    float acc[4][7] = {};
    for (int kt = 0; kt < 32; kt++) {
        int k0 = kt * 16;
        {
            int kk = tid >> 4, b4 = (tid & 15) * 4;
            *(float4*)&Ash[kk][b4] = *(const float4*)(slabA + (size_t)(k0 + kk) * 64 + b4);
        }
#pragma unroll
        for (int i = 0; i < 7; i++) {
            int idx = i * 256 + tid;
            int nn = idx >> 4, kk = idx & 15;
            Bsh[kk][nn] = g_Wcat[(size_t)nn * 512 + k0 + kk];
        }
        __syncthreads();
#pragma unroll
        for (int kk = 0; kk < 16; kk++) {
            float4 a = *(float4*)&Ash[kk][tm * 4];
#pragma unroll
            for (int j = 0; j < 7; j++) {
                float bv = Bsh[kk][tn * 7 + j];
                acc[0][j] += a.x * bv;
                acc[1][j] += a.y * bv;
                acc[2][j] += a.z * bv;
                acc[3][j] += a.w * bv;
            }
        }
        __syncthreads();
    }
#pragma unroll
    for (int i = 0; i < 4; i++) {
        int m = t * 64 + tm * 4 + i;
#pragma unroll
        for (int j = 0; j < 7; j++) {
            int n = tn * 7 + j;
            float v = acc[i][j];
            if (n < 34)       g_evbase[(size_t)m * NE + n]        = v + be[n];
            else if (n < 70)  g_base36[(size_t)m * NA + (n - 34)] = v + ba[n - 34];
            else if (n < 106) g_thadd [(size_t)m * NA + (n - 70)] = v;
        }
    }
}

// ---------------- kernel 5: event chains (prefetched) ----------------
__global__ void k_stageA(float* __restrict__ out_ev) {
    __shared__ float was[33 * 34];
    int tid = threadIdx.x;
    int b = tid >> 2, q = tid & 3;
    for (int i = tid; i < 33 * 34; i += 256) was[i] = g_WeGT[i];
    __syncthreads();
    int n0 = q * 9;
    int cnt = (q == 3) ? 7 : 9;
    float ctrg[9], cur[9];
#pragma unroll
    for (int i = 0; i < 9; i++) { ctrg[i] = 0.f; cur[i] = -1e30f; }
    {
        const float* eb = &g_evbase[(size_t)b * NE + n0];
#pragma unroll
        for (int i = 0; i < 9; i++) if (i < cnt) cur[i] = eb[i];
    }
    unsigned long long bits = 0ull;
    for (int t = 0; t < LL; t++) {
        float nxt[9];
        if (t < LL - 1) {
            const float* eb = &g_evbase[(size_t)((t + 1) * 64 + b) * NE + n0];
#pragma unroll
            for (int i = 0; i < 9; i++) if (i < cnt) nxt[i] = eb[i];
        }
        float o[9];
        float bestv = -1e30f;
        int besti = 1000;
#pragma unroll
        for (int i = 0; i < 9; i++) {
            if (i < cnt) {
                o[i] = cur[i] + ctrg[i];
                if (o[i] > bestv) { bestv = o[i]; besti = n0 + i; }
            }
        }
#pragma unroll
        for (int off = 1; off < 4; off <<= 1) {
            float ov = __shfl_xor_sync(0xffffffffu, bestv, off, 4);
            int   oi = __shfl_xor_sync(0xffffffffu, besti, off, 4);
            if (ov > bestv || (ov == bestv && oi < besti)) { bestv = ov; besti = oi; }
        }
        float* ob = &out_ev[((size_t)b * LL + t) * NE + n0];
#pragma unroll
        for (int i = 0; i < 9; i++) if (i < cnt) ob[i] = o[i];
        if (q == 0) g_emask[b * LL + t] = (besti > 0) ? 1 : 0;
        if (besti > 0) {
            int j = besti - 1;
            if (!((bits >> j) & 1ull)) {
                bits |= 1ull << j;
#pragma unroll
                for (int i = 0; i < 9; i++) if (i < cnt) ctrg[i] += was[j * NE + n0 + i];
            }
        }
#pragma unroll
        for (int i = 0; i < 9; i++) if (i < cnt) cur[i] = nxt[i];
    }
}

// ---------------- kernel 6: argument chains (staged coalesced output + prefetch) ----------------
__global__ void k_stageB(float* __restrict__ out_arg) {
    __shared__ float was[35 * 36];
    __shared__ unsigned char em[LL];
    __shared__ float sbuf[64 * 36];
    int bx = blockIdx.x;
    int b = bx >> 1, ph = bx & 1;
    int tid = threadIdx.x;
    int p = tid >> 2;
    int pos = ph * 64 + p;
    int q = tid & 3;
    int n0 = q * 9;
    if (tid < LL) em[tid] = g_emask[b * LL + tid];
    for (int i = tid; i < 35 * 36; i += 256) was[i] = g_WaGT[i];
    __syncthreads();

    float base[9], C[9], thc[9];
    const float* bp = &g_base36[(size_t)(pos * 64 + b) * NA + n0];
#pragma unroll
    for (int i = 0; i < 9; i++) { base[i] = bp[i]; C[i] = 0.f; }
    {
        const float* th = &g_thadd[(size_t)b * NA + n0];
#pragma unroll
        for (int i = 0; i < 9; i++) thc[i] = th[i];
    }
    unsigned long long bits = 0ull;

    for (int t = 0; t < LL; t++) {
        float thn[9];
        if (t < LL - 1) {
            const float* th = &g_thadd[(size_t)((t + 1) * 64 + b) * NA + n0];
#pragma unroll
            for (int i = 0; i < 9; i++) thn[i] = th[i];
        }
        float o[9];
        float bestv = -1e30f;
        int besti = 1000;
#pragma unroll
        for (int i = 0; i < 9; i++) {
            o[i] = base[i] + C[i] + thc[i];
            if (o[i] > bestv) { bestv = o[i]; besti = n0 + i; }
        }
#pragma unroll
        for (int off = 1; off < 4; off <<= 1) {
            float ov = __shfl_xor_sync(0xffffffffu, bestv, off, 4);
            int   oi = __shfl_xor_sync(0xffffffffu, besti, off, 4);
            if (ov > bestv || (ov == bestv && oi < besti)) { bestv = ov; besti = oi; }
        }
        float* sb = &sbuf[p * 36 + n0];
#pragma unroll
        for (int i = 0; i < 9; i++) sb[i] = o[i];
        if (em[t] && besti > 0) {
            int j = besti - 1;
            if (!((bits >> j) & 1ull)) {
                bits |= 1ull << j;
#pragma unroll
                for (int i = 0; i < 9; i++) C[i] += was[j * NA + n0 + i];
            }
        }
        __syncthreads();
        const float4* sb4 = (const float4*)sbuf;
        float4* og = (float4*)(out_arg + ((size_t)(b * LL + t) * LL + ph * 64) * NA);
#pragma unroll
        for (int i2 = tid; i2 < 576; i2 += 256) og[i2] = sb4[i2];
        __syncthreads();
#pragma unroll
        for (int i = 0; i < 9; i++) thc[i] = thn[i];
    }
}

// ---------------- launch ----------------
extern "C" void kernel_launch(void* const* d_in, const int* in_sizes, int n_in,
                              void* d_out, int out_size) {
    const int*   ids  = (const int*)  d_in[0];
    const float* emb  = (const float*)d_in[1];
    const float* Wihf = (const float*)d_in[2];
    const float* Whhf = (const float*)d_in[3];
    const float* bf   = (const float*)d_in[4];
    const float* Wihb = (const float*)d_in[5];
    const float* Whhb = (const float*)d_in[6];
    const float* bbv  = (const float*)d_in[7];
    const float* We   = (const float*)d_in[8];
    const float* be   = (const float*)d_in[9];
    const float* Wa   = (const float*)d_in[10];
    const float* ba   = (const float*)d_in[11];

    float* out_ev  = (float*)d_out;
    float* out_arg = out_ev + (size_t)BB * LL * NE;

    const int lstm_smem = 65536 + 16 * 258 * 4;   // 82048 B
    cudaFuncSetAttribute(k_lstm_all, cudaFuncAttributeMaxDynamicSharedMemorySize, lstm_smem);

    k_prep_all<<<832, 256>>>(ids, emb, Wihf, Wihb, We, Wa);
    k_gemm1<<<dim3(16, 64), 256>>>(bf, bbv);
    k_lstm_all<<<128, 256, lstm_smem>>>(Whhf, Whhb);
    k_gemm2<<<128, 256>>>(be, ba);
    k_stageA<<<1, 256>>>(out_ev);
    k_stageB<<<128, 256>>>(out_arg);
}